// round 7
// baseline (speedup 1.0000x reference)
#include <cuda_runtime.h>
#include <cuda_bf16.h>
#include <cstdint>

// Problem constants
#define NNODES 100000
#define NPAD   100096          // multiple of 128
#define INF 14
#define HID 256
#define K2  512                // concat K for layer-2 GEMM

// ---------------- scratch (device globals; no runtime allocation) -------------
__device__ float g_agg1[(size_t)NNODES * INF];
__device__ float g_h1  [(size_t)NNODES * HID];
__device__ float g_agg2[(size_t)NNODES * HID];
// bf16 split operands.  A = [agg2 | h1]  (NPAD x 512), B = [W2_rel;W2_root]^T (256 x 512)
__device__ __nv_bfloat16 g_Ahi[(size_t)NPAD * K2];
__device__ __nv_bfloat16 g_Alo[(size_t)NPAD * K2];
__device__ __nv_bfloat16 g_Bhi[(size_t)HID * K2];
__device__ __nv_bfloat16 g_Blo[(size_t)HID * K2];

__device__ __forceinline__ float selu_f(float v) {
    const float scale = 1.0507009873554804934193349852946f;
    const float alpha = 1.6732632423543772848170429916717f;
    return v > 0.f ? scale * v : scale * alpha * (__expf(v) - 1.f);
}

__device__ __forceinline__ void split_bf16(float v, __nv_bfloat16& hi, __nv_bfloat16& lo) {
    hi = __float2bfloat16(v);
    lo = __float2bfloat16(v - __bfloat162float(hi));
}

// ---------------- 0: zero ----------------------------------------------------
__global__ void zero_kernel(float* __restrict__ p, size_t n4) {
    size_t i = (size_t)blockIdx.x * blockDim.x + threadIdx.x;
    size_t stride = (size_t)gridDim.x * blockDim.x;
    float4 z = make_float4(0.f, 0.f, 0.f, 0.f);
    for (; i < n4; i += stride) ((float4*)p)[i] = z;
}

// ---------------- 1: edge aggregation, layer 1 (14 features) -----------------
__global__ void edge1_kernel(const int* __restrict__ ei,
                             const float* __restrict__ x,
                             float* __restrict__ agg1, int E) {
    int e = blockIdx.x * blockDim.x + threadIdx.x;
    if (e >= E) return;
    int src = ei[e];
    int dst = ei[(size_t)E + e];
    const float* xs = x + (size_t)src * INF;
    float* d = agg1 + (size_t)dst * INF;
#pragma unroll
    for (int f = 0; f < INF; f++) atomicAdd(d + f, xs[f]);
}

// ---------------- 2: fused dense layer 1 + selu + bf16 split -----------------
__global__ void dense1_kernel(const float* __restrict__ x,
                              const float* __restrict__ agg1,
                              const float* __restrict__ W_rel,
                              const float* __restrict__ b,
                              const float* __restrict__ W_root,
                              float* __restrict__ h1,
                              __nv_bfloat16* __restrict__ Ahi,
                              __nv_bfloat16* __restrict__ Alo, int N) {
    __shared__ float sx[32][INF];
    __shared__ float sa[32][INF];
    int tid = threadIdx.x;

    float wrel[INF], wroot[INF];
#pragma unroll
    for (int k = 0; k < INF; k++) {
        wrel[k]  = W_rel [k * HID + tid];
        wroot[k] = W_root[k * HID + tid];
    }
    float bj = b[tid];

    int node0 = blockIdx.x * 32;
    for (int i = tid; i < 32 * INF; i += 256) {
        int n = i / INF, f = i % INF;
        int g = node0 + n;
        if (g < N) {
            sx[n][f] = x   [(size_t)g * INF + f];
            sa[n][f] = agg1[(size_t)g * INF + f];
        }
    }
    __syncthreads();

#pragma unroll 4
    for (int n = 0; n < 32; n++) {
        int g = node0 + n;
        if (g >= N) break;
        float acc = bj;
#pragma unroll
        for (int k = 0; k < INF; k++)
            acc += sa[n][k] * wrel[k] + sx[n][k] * wroot[k];
        float v = selu_f(acc);
        h1[(size_t)g * HID + tid] = v;
        __nv_bfloat16 hi, lo;
        split_bf16(v, hi, lo);
        Ahi[(size_t)g * K2 + HID + tid] = hi;   // h1 -> K columns 256..511
        Alo[(size_t)g * K2 + HID + tid] = lo;
    }
}

// ---------------- 3: edge aggregation, layer 2 (vector red, no return) -------
__global__ void edge2_kernel(const int* __restrict__ ei,
                             const float* __restrict__ h1,
                             float* __restrict__ agg2, int E) {
    long long idx = (long long)blockIdx.x * blockDim.x + threadIdx.x;
    long long total = (long long)E * 64;
    if (idx >= total) return;
    int e = (int)(idx >> 6);
    int c = (int)(idx & 63) << 2;
    int src = __ldg(ei + e);
    int dst = __ldg(ei + (size_t)E + e);
    float4 v = *(const float4*)(h1 + (size_t)src * HID + c);
    float* d = agg2 + (size_t)dst * HID + c;
    asm volatile("red.global.add.v4.f32 [%0], {%1,%2,%3,%4};"
                 :: "l"(d), "f"(v.x), "f"(v.y), "f"(v.z), "f"(v.w) : "memory");
}

// ---------------- 3b: split agg2 -> bf16 hi/lo into A columns 0..255 ---------
__global__ void splitA_kernel(const float* __restrict__ agg2,
                              __nv_bfloat16* __restrict__ Ahi,
                              __nv_bfloat16* __restrict__ Alo, int N) {
    size_t i4 = (size_t)blockIdx.x * blockDim.x + threadIdx.x;
    size_t n4 = (size_t)N * HID / 4;
    size_t stride = (size_t)gridDim.x * blockDim.x;
    for (; i4 < n4; i4 += stride) {
        float4 v = ((const float4*)agg2)[i4];
        size_t row = i4 >> 6;
        int col = (int)(i4 & 63) << 2;
        __nv_bfloat16 h0, l0, h1_, l1, h2, l2, h3, l3;
        split_bf16(v.x, h0, l0); split_bf16(v.y, h1_, l1);
        split_bf16(v.z, h2, l2); split_bf16(v.w, h3, l3);
        __nv_bfloat162 ha = {h0, h1_}, hb = {h2, h3};
        __nv_bfloat162 la = {l0, l1},  lb = {l2, l3};
        *(uint2*)(Ahi + row * K2 + col) = make_uint2(*(uint32_t*)&ha, *(uint32_t*)&hb);
        *(uint2*)(Alo + row * K2 + col) = make_uint2(*(uint32_t*)&la, *(uint32_t*)&lb);
    }
}

// ---------------- 3c: B = [W2_rel ; W2_root]^T as [N=256][K=512] bf16 hi/lo --
__global__ void splitB_kernel(const float* __restrict__ W2_rel,
                              const float* __restrict__ W2_root,
                              __nv_bfloat16* __restrict__ Bhi,
                              __nv_bfloat16* __restrict__ Blo) {
    int idx = blockIdx.x * blockDim.x + threadIdx.x;
    if (idx >= HID * K2) return;
    int n = idx >> 9;
    int k = idx & (K2 - 1);
    float v = (k < HID) ? W2_rel[(size_t)k * HID + n]
                        : W2_root[(size_t)(k - HID) * HID + n];
    __nv_bfloat16 hi, lo;
    split_bf16(v, hi, lo);
    Bhi[idx] = hi;
    Blo[idx] = lo;
}

// ---------------- 4: mma.sync split-bf16 GEMM + bias + selu ------------------
// C[M,256] = selu(A @ B^T + bias).  BM=128, BN=128, BK=32, 8 warps (4x2),
// warp tile 32x64, m16n8k16 HMMA, 3 passes (hi*hi, hi*lo, lo*hi).
#define BK 32
#define LDA 40          // padded smem row stride (bf16): 80B, 16B-aligned, conflict-free

__device__ __forceinline__ void mma_bf16(float* d, const uint32_t* a, const uint32_t* b) {
    asm volatile(
        "mma.sync.aligned.m16n8k16.row.col.f32.bf16.bf16.f32 "
        "{%0,%1,%2,%3}, {%4,%5,%6,%7}, {%8,%9}, {%0,%1,%2,%3};"
        : "+f"(d[0]), "+f"(d[1]), "+f"(d[2]), "+f"(d[3])
        : "r"(a[0]), "r"(a[1]), "r"(a[2]), "r"(a[3]), "r"(b[0]), "r"(b[1]));
}

__global__ void __launch_bounds__(256, 1)
gemm2_tc_kernel(const __nv_bfloat16* __restrict__ gAhi,
                const __nv_bfloat16* __restrict__ gAlo,
                const __nv_bfloat16* __restrict__ gBhi,
                const __nv_bfloat16* __restrict__ gBlo,
                const float* __restrict__ bias,
                float* __restrict__ C, int M) {
    __shared__ __nv_bfloat16 sAhi[128 * LDA];
    __shared__ __nv_bfloat16 sAlo[128 * LDA];
    __shared__ __nv_bfloat16 sBhi[128 * LDA];
    __shared__ __nv_bfloat16 sBlo[128 * LDA];

    int tid = threadIdx.x;
    int wid = tid >> 5;
    int lane = tid & 31;
    int warp_m = wid & 3;        // 4 warps along M (32 rows each)
    int warp_n = wid >> 2;       // 2 warps along N (64 cols each)
    int r  = lane >> 2;          // 0..7
    int c2 = (lane & 3) << 1;    // 0,2,4,6

    int bm = blockIdx.x * 128;
    int bn = blockIdx.y * 128;

    float acc[2][8][4] = {};

    for (int kt = 0; kt < K2; kt += BK) {
        // ---- load 4 tiles: 128 rows x 32 bf16 each (4 uint4 per row) ----
#pragma unroll
        for (int p = 0; p < 2; p++) {
            int q = p * 256 + tid;       // 0..511
            int row = q >> 2;
            int seg = (q & 3) << 3;      // bf16 offset 0,8,16,24
            size_t ga = (size_t)(bm + row) * K2 + kt + seg;
            size_t gb = (size_t)(bn + row) * K2 + kt + seg;
            *(uint4*)&sAhi[row * LDA + seg] = *(const uint4*)(gAhi + ga);
            *(uint4*)&sAlo[row * LDA + seg] = *(const uint4*)(gAlo + ga);
            *(uint4*)&sBhi[row * LDA + seg] = *(const uint4*)(gBhi + gb);
            *(uint4*)&sBlo[row * LDA + seg] = *(const uint4*)(gBlo + gb);
        }
        __syncthreads();

#pragma unroll
        for (int kk = 0; kk < BK; kk += 16) {
            uint32_t ah[2][4], al[2][4], bh[8][2], bl[8][2];
#pragma unroll
            for (int i = 0; i < 2; i++) {
                int rb = warp_m * 32 + i * 16;
                ah[i][0] = *(const uint32_t*)&sAhi[(rb + r    ) * LDA + kk + c2];
                ah[i][1] = *(const uint32_t*)&sAhi[(rb + r + 8) * LDA + kk + c2];
                ah[i][2] = *(const uint32_t*)&sAhi[(rb + r    ) * LDA + kk + c2 + 8];
                ah[i][3] = *(const uint32_t*)&sAhi[(rb + r + 8) * LDA + kk + c2 + 8];
                al[i][0] = *(const uint32_t*)&sAlo[(rb + r    ) * LDA + kk + c2];
                al[i][1] = *(const uint32_t*)&sAlo[(rb + r + 8) * LDA + kk + c2];
                al[i][2] = *(const uint32_t*)&sAlo[(rb + r    ) * LDA + kk + c2 + 8];
                al[i][3] = *(const uint32_t*)&sAlo[(rb + r + 8) * LDA + kk + c2 + 8];
            }
#pragma unroll
            for (int j = 0; j < 8; j++) {
                int n = warp_n * 64 + j * 8 + r;
                bh[j][0] = *(const uint32_t*)&sBhi[n * LDA + kk + c2];
                bh[j][1] = *(const uint32_t*)&sBhi[n * LDA + kk + c2 + 8];
                bl[j][0] = *(const uint32_t*)&sBlo[n * LDA + kk + c2];
                bl[j][1] = *(const uint32_t*)&sBlo[n * LDA + kk + c2 + 8];
            }
#pragma unroll
            for (int i = 0; i < 2; i++)
#pragma unroll
                for (int j = 0; j < 8; j++) {
                    mma_bf16(acc[i][j], ah[i], bh[j]);   // hi*hi
                    mma_bf16(acc[i][j], ah[i], bl[j]);   // hi*lo
                    mma_bf16(acc[i][j], al[i], bh[j]);   // lo*hi
                }
        }
        __syncthreads();
    }

    // ---- epilogue: bias + selu, float2 stores ----
#pragma unroll
    for (int i = 0; i < 2; i++) {
        int row0 = bm + warp_m * 32 + i * 16 + r;
#pragma unroll
        for (int j = 0; j < 8; j++) {
            int col = bn + warp_n * 64 + j * 8 + c2;
            float b0 = bias[col], b1 = bias[col + 1];
            if (row0 < M) {
                float2 o = { selu_f(acc[i][j][0] + b0), selu_f(acc[i][j][1] + b1) };
                *(float2*)(C + (size_t)row0 * HID + col) = o;
            }
            if (row0 + 8 < M) {
                float2 o = { selu_f(acc[i][j][2] + b0), selu_f(acc[i][j][3] + b1) };
                *(float2*)(C + (size_t)(row0 + 8) * HID + col) = o;
            }
        }
    }
}

// ---------------------------------------------------------------------------
extern "C" void kernel_launch(void* const* d_in, const int* in_sizes, int n_in,
                              void* d_out, int out_size) {
    const float* x      = (const float*)d_in[0];
    const int*   ei     = (const int*)d_in[1];   // int32 on device
    const float* W1_rel = (const float*)d_in[3];
    const float* b1     = (const float*)d_in[4];
    const float* W1_root= (const float*)d_in[5];
    const float* W2_rel = (const float*)d_in[6];
    const float* b2     = (const float*)d_in[7];
    const float* W2_root= (const float*)d_in[8];
    float* out = (float*)d_out;

    int N = in_sizes[0] / INF;
    int E = in_sizes[1] / 2;

    float *agg1, *h1, *agg2;
    __nv_bfloat16 *Ahi, *Alo, *Bhi, *Blo;
    cudaGetSymbolAddress((void**)&agg1, g_agg1);
    cudaGetSymbolAddress((void**)&h1,   g_h1);
    cudaGetSymbolAddress((void**)&agg2, g_agg2);
    cudaGetSymbolAddress((void**)&Ahi,  g_Ahi);
    cudaGetSymbolAddress((void**)&Alo,  g_Alo);
    cudaGetSymbolAddress((void**)&Bhi,  g_Bhi);
    cudaGetSymbolAddress((void**)&Blo,  g_Blo);

    // 0: zero agg buffers
    zero_kernel<<<1024, 256>>>(agg1, ((size_t)N * INF + 3) / 4);
    zero_kernel<<<2048, 256>>>(agg2, (size_t)N * HID / 4);

    // B split (tiny, independent)
    splitB_kernel<<<(HID * K2 + 255) / 256, 256>>>(W2_rel, W2_root, Bhi, Blo);

    // 1: layer-1 edge aggregation
    edge1_kernel<<<(E + 255) / 256, 256>>>(ei, x, agg1, E);

    // 2: layer-1 dense + selu -> h1 (+ bf16 split into A cols 256..511)
    dense1_kernel<<<(N + 31) / 32, 256>>>(x, agg1, W1_rel, b1, W1_root, h1, Ahi, Alo, N);

    // 3: layer-2 edge aggregation (vector red)
    {
        long long total = (long long)E * 64;
        edge2_kernel<<<(int)((total + 255) / 256), 256>>>(ei, h1, agg2, E);
    }

    // 3b: split agg2 into A cols 0..255
    splitA_kernel<<<2048, 256>>>(agg2, Ahi, Alo, N);

    // 4: tensor-core split-bf16 GEMM + bias + selu
    {
        dim3 grid((N + 127) / 128, HID / 128);
        gemm2_tc_kernel<<<grid, 256>>>(Ahi, Alo, Bhi, Blo, b2, out, N);
    }
}

// round 8
// speedup vs baseline: 1.0018x; 1.0018x over previous
#include <cuda_runtime.h>
#include <cuda_bf16.h>
#include <cstdint>

// Problem constants
#define NNODES 100000
#define NPAD   100096          // multiple of 128
#define INF 14
#define HID 256
#define K2  512                // concat K for layer-2 GEMM

// ---------------- scratch (device globals; no runtime allocation) -------------
__device__ float g_agg1[(size_t)NNODES * INF];
__device__ float g_h1  [(size_t)NNODES * HID];
__device__ float g_agg2[(size_t)NNODES * HID];
// bf16 split operands.  A = [agg2 | h1]  (NPAD x 512), B = [W2_rel;W2_root]^T (256 x 512)
__device__ __nv_bfloat16 g_Ahi[(size_t)NPAD * K2];
__device__ __nv_bfloat16 g_Alo[(size_t)NPAD * K2];
__device__ __nv_bfloat16 g_Bhi[(size_t)HID * K2];
__device__ __nv_bfloat16 g_Blo[(size_t)HID * K2];

__device__ __forceinline__ float selu_f(float v) {
    const float scale = 1.0507009873554804934193349852946f;
    const float alpha = 1.6732632423543772848170429916717f;
    return v > 0.f ? scale * v : scale * alpha * (__expf(v) - 1.f);
}

__device__ __forceinline__ void split_bf16(float v, __nv_bfloat16& hi, __nv_bfloat16& lo) {
    hi = __float2bfloat16(v);
    lo = __float2bfloat16(v - __bfloat162float(hi));
}

// ---------------- 0: zero ----------------------------------------------------
__global__ void zero_kernel(float* __restrict__ p, size_t n4) {
    size_t i = (size_t)blockIdx.x * blockDim.x + threadIdx.x;
    size_t stride = (size_t)gridDim.x * blockDim.x;
    float4 z = make_float4(0.f, 0.f, 0.f, 0.f);
    for (; i < n4; i += stride) ((float4*)p)[i] = z;
}

// ---------------- 1: edge aggregation, layer 1 (14 features) -----------------
__global__ void edge1_kernel(const int* __restrict__ ei,
                             const float* __restrict__ x,
                             float* __restrict__ agg1, int E) {
    int e = blockIdx.x * blockDim.x + threadIdx.x;
    if (e >= E) return;
    int src = ei[e];
    int dst = ei[(size_t)E + e];
    const float* xs = x + (size_t)src * INF;
    float* d = agg1 + (size_t)dst * INF;
#pragma unroll
    for (int f = 0; f < INF; f++) atomicAdd(d + f, xs[f]);
}

// ---------------- 2: fused dense layer 1 + selu + bf16 split -----------------
__global__ void dense1_kernel(const float* __restrict__ x,
                              const float* __restrict__ agg1,
                              const float* __restrict__ W_rel,
                              const float* __restrict__ b,
                              const float* __restrict__ W_root,
                              float* __restrict__ h1,
                              __nv_bfloat16* __restrict__ Ahi,
                              __nv_bfloat16* __restrict__ Alo, int N) {
    __shared__ float sx[32][INF];
    __shared__ float sa[32][INF];
    int tid = threadIdx.x;

    float wrel[INF], wroot[INF];
#pragma unroll
    for (int k = 0; k < INF; k++) {
        wrel[k]  = W_rel [k * HID + tid];
        wroot[k] = W_root[k * HID + tid];
    }
    float bj = b[tid];

    int node0 = blockIdx.x * 32;
    for (int i = tid; i < 32 * INF; i += 256) {
        int n = i / INF, f = i % INF;
        int g = node0 + n;
        if (g < N) {
            sx[n][f] = x   [(size_t)g * INF + f];
            sa[n][f] = agg1[(size_t)g * INF + f];
        }
    }
    __syncthreads();

#pragma unroll 4
    for (int n = 0; n < 32; n++) {
        int g = node0 + n;
        if (g >= N) break;
        float acc = bj;
#pragma unroll
        for (int k = 0; k < INF; k++)
            acc += sa[n][k] * wrel[k] + sx[n][k] * wroot[k];
        float v = selu_f(acc);
        h1[(size_t)g * HID + tid] = v;
        __nv_bfloat16 hi, lo;
        split_bf16(v, hi, lo);
        Ahi[(size_t)g * K2 + HID + tid] = hi;   // h1 -> K columns 256..511
        Alo[(size_t)g * K2 + HID + tid] = lo;
    }
}

// ---------------- 3: edge aggregation, layer 2 (vector red, no return) -------
__global__ void edge2_kernel(const int* __restrict__ ei,
                             const float* __restrict__ h1,
                             float* __restrict__ agg2, int E) {
    long long idx = (long long)blockIdx.x * blockDim.x + threadIdx.x;
    long long total = (long long)E * 64;
    if (idx >= total) return;
    int e = (int)(idx >> 6);
    int c = (int)(idx & 63) << 2;
    int src = __ldg(ei + e);
    int dst = __ldg(ei + (size_t)E + e);
    float4 v = *(const float4*)(h1 + (size_t)src * HID + c);
    float* d = agg2 + (size_t)dst * HID + c;
    asm volatile("red.global.add.v4.f32 [%0], {%1,%2,%3,%4};"
                 :: "l"(d), "f"(v.x), "f"(v.y), "f"(v.z), "f"(v.w) : "memory");
}

// ---------------- 3b: split agg2 -> bf16 hi/lo into A columns 0..255 ---------
__global__ void splitA_kernel(const float* __restrict__ agg2,
                              __nv_bfloat16* __restrict__ Ahi,
                              __nv_bfloat16* __restrict__ Alo, int N) {
    size_t i4 = (size_t)blockIdx.x * blockDim.x + threadIdx.x;
    size_t n4 = (size_t)N * HID / 4;
    size_t stride = (size_t)gridDim.x * blockDim.x;
    for (; i4 < n4; i4 += stride) {
        float4 v = ((const float4*)agg2)[i4];
        size_t row = i4 >> 6;
        int col = (int)(i4 & 63) << 2;
        __nv_bfloat16 h0, l0, h1_, l1, h2, l2, h3, l3;
        split_bf16(v.x, h0, l0); split_bf16(v.y, h1_, l1);
        split_bf16(v.z, h2, l2); split_bf16(v.w, h3, l3);
        __nv_bfloat162 ha = {h0, h1_}, hb = {h2, h3};
        __nv_bfloat162 la = {l0, l1},  lb = {l2, l3};
        *(uint2*)(Ahi + row * K2 + col) = make_uint2(*(uint32_t*)&ha, *(uint32_t*)&hb);
        *(uint2*)(Alo + row * K2 + col) = make_uint2(*(uint32_t*)&la, *(uint32_t*)&lb);
    }
}

// ---------------- 3c: B = [W2_rel ; W2_root]^T as [N=256][K=512] bf16 hi/lo --
__global__ void splitB_kernel(const float* __restrict__ W2_rel,
                              const float* __restrict__ W2_root,
                              __nv_bfloat16* __restrict__ Bhi,
                              __nv_bfloat16* __restrict__ Blo) {
    int idx = blockIdx.x * blockDim.x + threadIdx.x;
    if (idx >= HID * K2) return;
    int n = idx >> 9;
    int k = idx & (K2 - 1);
    float v = (k < HID) ? W2_rel[(size_t)k * HID + n]
                        : W2_root[(size_t)(k - HID) * HID + n];
    __nv_bfloat16 hi, lo;
    split_bf16(v, hi, lo);
    Bhi[idx] = hi;
    Blo[idx] = lo;
}

// ---------------- 4: mma.sync split-bf16 GEMM + bias + selu ------------------
// C[M,256] = selu(A @ B^T + bias).  BM=128, BN=128, BK=32, 8 warps (4x2),
// warp tile 32x64, m16n8k16 HMMA, 3 passes (hi*hi, hi*lo, lo*hi).
#define BK 32
#define LDA 40          // padded smem row stride (bf16): 80B, 16B-aligned, conflict-free

__device__ __forceinline__ void mma_bf16(float* d, const uint32_t* a, const uint32_t* b) {
    asm volatile(
        "mma.sync.aligned.m16n8k16.row.col.f32.bf16.bf16.f32 "
        "{%0,%1,%2,%3}, {%4,%5,%6,%7}, {%8,%9}, {%0,%1,%2,%3};"
        : "+f"(d[0]), "+f"(d[1]), "+f"(d[2]), "+f"(d[3])
        : "r"(a[0]), "r"(a[1]), "r"(a[2]), "r"(a[3]), "r"(b[0]), "r"(b[1]));
}

__global__ void __launch_bounds__(256, 1)
gemm2_tc_kernel(const __nv_bfloat16* __restrict__ gAhi,
                const __nv_bfloat16* __restrict__ gAlo,
                const __nv_bfloat16* __restrict__ gBhi,
                const __nv_bfloat16* __restrict__ gBlo,
                const float* __restrict__ bias,
                float* __restrict__ C, int M) {
    __shared__ __nv_bfloat16 sAhi[128 * LDA];
    __shared__ __nv_bfloat16 sAlo[128 * LDA];
    __shared__ __nv_bfloat16 sBhi[128 * LDA];
    __shared__ __nv_bfloat16 sBlo[128 * LDA];

    int tid = threadIdx.x;
    int wid = tid >> 5;
    int lane = tid & 31;
    int warp_m = wid & 3;        // 4 warps along M (32 rows each)
    int warp_n = wid >> 2;       // 2 warps along N (64 cols each)
    int r  = lane >> 2;          // 0..7
    int c2 = (lane & 3) << 1;    // 0,2,4,6

    int bm = blockIdx.x * 128;
    int bn = blockIdx.y * 128;

    float acc[2][8][4] = {};

    for (int kt = 0; kt < K2; kt += BK) {
        // ---- load 4 tiles: 128 rows x 32 bf16 each (4 uint4 per row) ----
#pragma unroll
        for (int p = 0; p < 2; p++) {
            int q = p * 256 + tid;       // 0..511
            int row = q >> 2;
            int seg = (q & 3) << 3;      // bf16 offset 0,8,16,24
            size_t ga = (size_t)(bm + row) * K2 + kt + seg;
            size_t gb = (size_t)(bn + row) * K2 + kt + seg;
            *(uint4*)&sAhi[row * LDA + seg] = *(const uint4*)(gAhi + ga);
            *(uint4*)&sAlo[row * LDA + seg] = *(const uint4*)(gAlo + ga);
            *(uint4*)&sBhi[row * LDA + seg] = *(const uint4*)(gBhi + gb);
            *(uint4*)&sBlo[row * LDA + seg] = *(const uint4*)(gBlo + gb);
        }
        __syncthreads();

#pragma unroll
        for (int kk = 0; kk < BK; kk += 16) {
            uint32_t ah[2][4], al[2][4], bh[8][2], bl[8][2];
#pragma unroll
            for (int i = 0; i < 2; i++) {
                int rb = warp_m * 32 + i * 16;
                ah[i][0] = *(const uint32_t*)&sAhi[(rb + r    ) * LDA + kk + c2];
                ah[i][1] = *(const uint32_t*)&sAhi[(rb + r + 8) * LDA + kk + c2];
                ah[i][2] = *(const uint32_t*)&sAhi[(rb + r    ) * LDA + kk + c2 + 8];
                ah[i][3] = *(const uint32_t*)&sAhi[(rb + r + 8) * LDA + kk + c2 + 8];
                al[i][0] = *(const uint32_t*)&sAlo[(rb + r    ) * LDA + kk + c2];
                al[i][1] = *(const uint32_t*)&sAlo[(rb + r + 8) * LDA + kk + c2];
                al[i][2] = *(const uint32_t*)&sAlo[(rb + r    ) * LDA + kk + c2 + 8];
                al[i][3] = *(const uint32_t*)&sAlo[(rb + r + 8) * LDA + kk + c2 + 8];
            }
#pragma unroll
            for (int j = 0; j < 8; j++) {
                int n = warp_n * 64 + j * 8 + r;
                bh[j][0] = *(const uint32_t*)&sBhi[n * LDA + kk + c2];
                bh[j][1] = *(const uint32_t*)&sBhi[n * LDA + kk + c2 + 8];
                bl[j][0] = *(const uint32_t*)&sBlo[n * LDA + kk + c2];
                bl[j][1] = *(const uint32_t*)&sBlo[n * LDA + kk + c2 + 8];
            }
#pragma unroll
            for (int i = 0; i < 2; i++)
#pragma unroll
                for (int j = 0; j < 8; j++) {
                    mma_bf16(acc[i][j], ah[i], bh[j]);   // hi*hi
                    mma_bf16(acc[i][j], ah[i], bl[j]);   // hi*lo
                    mma_bf16(acc[i][j], al[i], bh[j]);   // lo*hi
                }
        }
        __syncthreads();
    }

    // ---- epilogue: bias + selu, float2 stores ----
#pragma unroll
    for (int i = 0; i < 2; i++) {
        int row0 = bm + warp_m * 32 + i * 16 + r;
#pragma unroll
        for (int j = 0; j < 8; j++) {
            int col = bn + warp_n * 64 + j * 8 + c2;
            float b0 = bias[col], b1 = bias[col + 1];
            if (row0 < M) {
                float2 o = { selu_f(acc[i][j][0] + b0), selu_f(acc[i][j][1] + b1) };
                *(float2*)(C + (size_t)row0 * HID + col) = o;
            }
            if (row0 + 8 < M) {
                float2 o = { selu_f(acc[i][j][2] + b0), selu_f(acc[i][j][3] + b1) };
                *(float2*)(C + (size_t)(row0 + 8) * HID + col) = o;
            }
        }
    }
}

// ---------------------------------------------------------------------------
extern "C" void kernel_launch(void* const* d_in, const int* in_sizes, int n_in,
                              void* d_out, int out_size) {
    const float* x      = (const float*)d_in[0];
    const int*   ei     = (const int*)d_in[1];   // int32 on device
    const float* W1_rel = (const float*)d_in[3];
    const float* b1     = (const float*)d_in[4];
    const float* W1_root= (const float*)d_in[5];
    const float* W2_rel = (const float*)d_in[6];
    const float* b2     = (const float*)d_in[7];
    const float* W2_root= (const float*)d_in[8];
    float* out = (float*)d_out;

    int N = in_sizes[0] / INF;
    int E = in_sizes[1] / 2;

    float *agg1, *h1, *agg2;
    __nv_bfloat16 *Ahi, *Alo, *Bhi, *Blo;
    cudaGetSymbolAddress((void**)&agg1, g_agg1);
    cudaGetSymbolAddress((void**)&h1,   g_h1);
    cudaGetSymbolAddress((void**)&agg2, g_agg2);
    cudaGetSymbolAddress((void**)&Ahi,  g_Ahi);
    cudaGetSymbolAddress((void**)&Alo,  g_Alo);
    cudaGetSymbolAddress((void**)&Bhi,  g_Bhi);
    cudaGetSymbolAddress((void**)&Blo,  g_Blo);

    // 0: zero agg buffers
    zero_kernel<<<1024, 256>>>(agg1, ((size_t)N * INF + 3) / 4);
    zero_kernel<<<2048, 256>>>(agg2, (size_t)N * HID / 4);

    // B split (tiny, independent)
    splitB_kernel<<<(HID * K2 + 255) / 256, 256>>>(W2_rel, W2_root, Bhi, Blo);

    // 1: layer-1 edge aggregation
    edge1_kernel<<<(E + 255) / 256, 256>>>(ei, x, agg1, E);

    // 2: layer-1 dense + selu -> h1 (+ bf16 split into A cols 256..511)
    dense1_kernel<<<(N + 31) / 32, 256>>>(x, agg1, W1_rel, b1, W1_root, h1, Ahi, Alo, N);

    // 3: layer-2 edge aggregation (vector red)
    {
        long long total = (long long)E * 64;
        edge2_kernel<<<(int)((total + 255) / 256), 256>>>(ei, h1, agg2, E);
    }

    // 3b: split agg2 into A cols 0..255
    splitA_kernel<<<2048, 256>>>(agg2, Ahi, Alo, N);

    // 4: tensor-core split-bf16 GEMM + bias + selu
    {
        dim3 grid((N + 127) / 128, HID / 128);
        gemm2_tc_kernel<<<grid, 256>>>(Ahi, Alo, Bhi, Blo, b2, out, N);
    }
}